// round 16
// baseline (speedup 1.0000x reference)
#include <cuda_runtime.h>

// out[e] for linear e in [0, B*8*513*513):
//   decode p = e/513^2 (plane = b*8+h), rem = e - p*513^2, r = rem/513,
//   c = rem - 513r. Value = token[h] if r==0||c==0 else
//   emb[ st[b*512^2 + (r-1)*512 + (c-1)] ][h].
//
// Iteration is over 128B-ALIGNED output windows: warp owns 128 consecutive
// floats (4 full lines), lane handles 4 elements at stride 32. All stores are
// full-line aligned (previous kernels split every warp store across 2 lines,
// 5 sectors, 2 partial -> ~2x store wavefronts + partial-sector L2 merges on
// 135MB of writes). st loads stay coalesced (consecutive e -> consecutive c).
// emb gathered from smem, transposed at odd pitch (uniform banks for random s).
// Divisors are compile-time (N=512 specialization) -> magic multiplies.

__global__ void __launch_bounds__(512)
wbe_lin(const int* __restrict__ st,
        const float* __restrict__ emb,
        const float* __restrict__ token,
        float* __restrict__ out,
        int total, int embRows, int pitch)
{
    constexpr unsigned PLANE = 513u * 513u;   // 263169
    constexpr unsigned NP1   = 513u;

    extern __shared__ float sh[];             // 8*pitch floats, then 8 token floats
    float* s_embT = sh;
    float* s_tok  = sh + 8 * pitch;

    const int tid = threadIdx.x;

    // Stage emb transposed via float4 loads: 4x fewer staging LDGs.
    {
        const float4* e4 = reinterpret_cast<const float4*>(emb);
        const int nv4 = embRows * 2;          // embRows*8 floats / 4
        for (int i = tid; i < nv4; i += blockDim.x) {
            float4 v = e4[i];
            int base = i * 4;                 // element index into emb[s*8+h]
            float vv[4] = {v.x, v.y, v.z, v.w};
            #pragma unroll
            for (int j = 0; j < 4; ++j) {
                int el = base + j;
                s_embT[(el & 7) * pitch + (el >> 3)] = vv[j];
            }
        }
        if (tid < 8) s_tok[tid] = token[tid];
    }
    __syncthreads();

    // Warp owns 128 consecutive floats; lane handles 4 elements stride 32.
    const int warp = tid >> 5;
    const int lane = tid & 31;
    const int e0 = blockIdx.x * 2048 + warp * 128 + lane;

    int   sv[4];
    int   hh[4];
    bool  isTok[4];
    bool  valid[4];

    // Pass 1: decode + issue all st loads (4 independent -> MLP 4).
    #pragma unroll
    for (int k = 0; k < 4; ++k) {
        const int e = e0 + 32 * k;
        valid[k] = (e < total);
        const unsigned ue  = (unsigned)e;
        const unsigned p   = ue / PLANE;              // magic multiply
        const unsigned rem = ue - p * PLANE;
        const unsigned r   = rem / NP1;               // magic multiply
        const unsigned c   = rem - r * NP1;
        hh[k] = (int)(p & 7u);
        isTok[k] = (r == 0u) | (c == 0u);
        sv[k] = 0;
        if (valid[k] && !isTok[k]) {
            const unsigned b = p >> 3;
            sv[k] = __ldg(&st[(b << 18) + ((r - 1u) << 9) + (c - 1u)]);
        }
    }

    // Pass 2: gather + full-line aligned stores.
    #pragma unroll
    for (int k = 0; k < 4; ++k) {
        if (!valid[k]) continue;
        const float val = isTok[k] ? s_tok[hh[k]]
                                   : s_embT[hh[k] * pitch + sv[k]];
        out[e0 + 32 * k] = val;
    }
}

// Generic fallback (safety net for unexpected shapes)
__global__ void wbe_kernel_generic(const int* __restrict__ st,
                                   const float* __restrict__ emb,
                                   const float* __restrict__ token,
                                   float* __restrict__ out,
                                   int B, int N, int H, int embRows,
                                   long long total)
{
    extern __shared__ float sh[];
    float* s_emb = sh;
    float* s_tok = sh + (size_t)embRows * H;
    const int nsh = embRows * H;
    for (int i = threadIdx.x; i < nsh; i += blockDim.x) s_emb[i] = emb[i];
    for (int i = threadIdx.x; i < H; i += blockDim.x) s_tok[i] = token[i];
    __syncthreads();

    long long idx = (long long)blockIdx.x * blockDim.x + threadIdx.x;
    if (idx >= total) return;

    const int Np1 = N + 1;
    int c = (int)(idx % Np1);
    long long t = idx / Np1;
    int r = (int)(t % Np1);
    int bb = (int)(t / Np1);

    const float* src;
    if (r == 0 || c == 0) {
        src = s_tok;
    } else {
        int stv = st[((long long)bb * N + (r - 1)) * N + (c - 1)];
        src = s_emb + (size_t)stv * H;
    }
    const long long plane = (long long)Np1 * Np1;
    long long o = ((long long)bb * H) * plane + (long long)r * Np1 + c;
    for (int hh = 0; hh < H; ++hh)
        out[o + (long long)hh * plane] = src[hh];
}

extern "C" void kernel_launch(void* const* d_in, const int* in_sizes, int n_in,
                              void* d_out, int out_size)
{
    // inputs (metadata order):
    // 0: spatial_types [E] int32, 1: graph_index [2,E] int32, 2: batch [B*N] int32,
    // 3: num_graphs, 4: max_nodes, 5: emb_weight [(S+1),H] f32, 6: graph_token [1,H,1] f32
    const int*   st    = (const int*)  d_in[0];
    const float* emb   = (const float*)d_in[5];
    const float* token = (const float*)d_in[6];
    float* out = (float*)d_out;

    const long long E = in_sizes[0];
    const int num_nodes = in_sizes[2];
    const int H = in_sizes[6];
    const int embRows = in_sizes[5] / H;
    const int N = (int)(E / num_nodes);   // E = B*N*N, num_nodes = B*N
    const int B = num_nodes / N;
    const int Np1 = N + 1;
    const long long total = (long long)B * H * Np1 * Np1;

    if (H == 8 && N == 512 && embRows <= 2048 && total < (1LL << 31)) {
        const int pitch = (embRows & 1) ? embRows : embRows + 1;
        const int itotal = (int)total;
        const int blocks = (itotal + 2047) / 2048;      // 512 thr * 4 elems
        const size_t smem = (size_t)(8 * pitch + 8) * sizeof(float);
        wbe_lin<<<blocks, 512, smem>>>(st, emb, token, out, itotal, embRows, pitch);
    } else {
        const int threads = 256;
        const long long blocks = (total / H + threads - 1) / threads;  // per (b,r,c)
        const long long totalBRC = (long long)B * Np1 * Np1;
        const long long blk = (totalBRC + threads - 1) / threads;
        const size_t smem = ((size_t)embRows * H + H) * sizeof(float);
        wbe_kernel_generic<<<(unsigned)blk, threads, smem>>>(
            st, emb, token, out, B, N, H, embRows, totalBRC);
        (void)blocks;
    }
}